// round 1
// baseline (speedup 1.0000x reference)
#include <cuda_runtime.h>

// CombinedGeneModel fused kernel.
// Reference math (per batch b, gene g, tech t, rows r_t = t*G + g):
//   h[e]  = relu(x[b,t,g] * w1[r_t,e] + b1[r_t,e])          e in [0,4)
//   s_t   = relu(sum_e h[e] * w2[r_t,e] + b2[r_t])
//   out   = relu(s_0 * wg[g,0] + s_1 * wg[g,1] + bg[g])
//
// Strategy: thread <-> gene. Load the ~29 weight floats for this gene once
// into registers, then stream BT batches (coalesced x loads / out stores).
// HBM traffic = x (163.8 MB) + out (81.9 MB); weights stay in L2/regs.

#define N_GENES 20000
#define N_BATCH 1024
#define BT      16     // batch tile per block
#define TPB     256    // threads per block

__device__ __forceinline__ float relu_f(float v) { return fmaxf(v, 0.0f); }

__device__ __forceinline__ float bellows(float x, float4 w1, float4 b1,
                                         float4 w2, float b2) {
    float h0 = relu_f(fmaf(x, w1.x, b1.x));
    float h1 = relu_f(fmaf(x, w1.y, b1.y));
    float h2 = relu_f(fmaf(x, w1.z, b1.z));
    float h3 = relu_f(fmaf(x, w1.w, b1.w));
    float s = b2;
    s = fmaf(h0, w2.x, s);
    s = fmaf(h1, w2.y, s);
    s = fmaf(h2, w2.z, s);
    s = fmaf(h3, w2.w, s);
    return relu_f(s);
}

__global__ __launch_bounds__(TPB)
void fused_gene_kernel(const float* __restrict__ x,
                       const float* __restrict__ w1,
                       const float* __restrict__ b1,
                       const float* __restrict__ w2,
                       const float* __restrict__ b2,
                       const float* __restrict__ wg,
                       const float* __restrict__ bg,
                       float* __restrict__ out)
{
    const int g = blockIdx.x * TPB + threadIdx.x;
    if (g >= N_GENES) return;
    const int b0 = blockIdx.y * BT;

    // Per-gene weights: tech0 row = g, tech1 row = N_GENES + g
    const float4* w1v = reinterpret_cast<const float4*>(w1);
    const float4* b1v = reinterpret_cast<const float4*>(b1);
    const float4* w2v = reinterpret_cast<const float4*>(w2);
    const float2* wgv = reinterpret_cast<const float2*>(wg);

    const float4 w1a = w1v[g];
    const float4 b1a = b1v[g];
    const float4 w2a = w2v[g];
    const float  b2a = b2[g];
    const float4 w1b = w1v[N_GENES + g];
    const float4 b1b = b1v[N_GENES + g];
    const float4 w2b = w2v[N_GENES + g];
    const float  b2b = b2[N_GENES + g];
    const float2 wgg = wgv[g];
    const float  bgg = bg[g];

    const float* __restrict__ xp = x + (size_t)b0 * (2 * N_GENES) + g;
    float* __restrict__ op = out + (size_t)b0 * N_GENES + g;

#pragma unroll
    for (int ib = 0; ib < BT; ++ib) {
        const float xv0 = xp[(size_t)ib * (2 * N_GENES)];
        const float xv1 = xp[(size_t)ib * (2 * N_GENES) + N_GENES];
        const float s0 = bellows(xv0, w1a, b1a, w2a, b2a);
        const float s1 = bellows(xv1, w1b, b1b, w2b, b2b);
        float o = bgg;
        o = fmaf(s0, wgg.x, o);
        o = fmaf(s1, wgg.y, o);
        op[(size_t)ib * N_GENES] = relu_f(o);
    }
}

extern "C" void kernel_launch(void* const* d_in, const int* in_sizes, int n_in,
                              void* d_out, int out_size)
{
    const float* x  = (const float*)d_in[0];  // [1024, 2, 20000]
    const float* w1 = (const float*)d_in[1];  // [40000, 4]
    const float* b1 = (const float*)d_in[2];  // [40000, 4]
    const float* w2 = (const float*)d_in[3];  // [40000, 4]
    const float* b2 = (const float*)d_in[4];  // [40000]
    const float* wg = (const float*)d_in[5];  // [20000, 2]
    const float* bg = (const float*)d_in[6];  // [20000]
    float* out = (float*)d_out;               // [1024, 20000]

    dim3 grid((N_GENES + TPB - 1) / TPB, N_BATCH / BT);
    fused_gene_kernel<<<grid, TPB>>>(x, w1, b1, w2, b2, wg, bg, out);
}